// round 11
// baseline (speedup 1.0000x reference)
#include <cuda_runtime.h>
#include <cuda_bf16.h>

#define NQ      10
#define DIM     1024
#define LAYERS  8
#define THREADS 512
#define PLANE   1088
#define CFS     12

typedef unsigned long long u64;

__device__ __forceinline__ int sp10(int x) {
    // suffix parity: bit p = XOR of bits p..9  (CNOT-chain permutation)
    x ^= x >> 1; x ^= x >> 2; x ^= x >> 4; x ^= x >> 8;
    return x;
}
__device__ __forceinline__ int padi(int j) { return j + 2 * (j >> 5); }  // even-pair-preserving

__device__ __forceinline__ u64 pfma(u64 a, u64 b, u64 c) {
    u64 d; asm("fma.rn.f32x2 %0, %1, %2, %3;" : "=l"(d) : "l"(a), "l"(b), "l"(c));
    return d;
}
__device__ __forceinline__ u64 pmul(u64 a, u64 b) {
    u64 d; asm("mul.rn.f32x2 %0, %1, %2;" : "=l"(d) : "l"(a), "l"(b));
    return d;
}
__device__ __forceinline__ u64 pack2(float lo, float hi) {
    u64 d; asm("mov.b64 %0, {%1, %2};" : "=l"(d) : "f"(lo), "f"(hi));
    return d;
}
__device__ __forceinline__ void unpack2(u64 v, float& lo, float& hi) {
    asm("mov.b64 {%0, %1}, %2;" : "=f"(lo), "=f"(hi) : "l"(v));
}
__device__ __forceinline__ u64 swap64(u64 v) {
    u64 r;
    asm("{ .reg .b32 lo, hi; mov.b64 {lo, hi}, %1; mov.b64 %0, {hi, lo}; }"
        : "=l"(r) : "l"(v));
    return r;
}
__device__ __forceinline__ u64 dup2(float v) { return pack2(v, v); }

// coefficient table per gate (u64 slots, identical to validated R10 layout):
// 0:A=dup(m11x) 1:B=dup(m11y) 2:NB=dup(-m11y) 3:C=dup(m12x) 4:NC=dup(-m12x)
// 5:D=dup(m12y) 6:ND=dup(-m12y) 7:Bmix=(m11y,-m11y) 8:NBmix=(-m11y,m11y)
// 9:Cmix=(m12x,-m12x)  [10,11 pad]

// Lane-shuffle gate on one SoA pack (2 amps). S = per-thread sign mask
// (0 or 0x80000000_80000000 from the gate's lane bit). Validated algebra (R10).
__device__ __forceinline__ void laneGate(u64& VX, u64& VY,
                                         int mask, const u64* g, u64 S)
{
    u64 ox = __shfl_xor_sync(0xffffffffu, VX, mask);
    u64 oy = __shfl_xor_sync(0xffffffffu, VY, mask);
    const u64 A = g[0], D = g[5], ND = g[6];
    const u64 Bs  = g[1] ^ S;
    const u64 NBs = g[2] ^ S;
    const u64 Cs  = g[3] ^ S;
    u64 nx = pfma(A, VX, pfma(NBs, VY, pfma(Cs, ox, pmul(ND, oy))));
    u64 ny = pfma(A, VY, pfma(Bs,  VX, pfma(Cs, oy, pmul(D,  ox))));
    VX = nx; VY = ny;
}

// Within-pack gate: the pack halves are the gate pair (half0 = gate-bit 0).
// Partner = half-swap; per-half signs baked into the mixed packs. Validated (R10).
__device__ __forceinline__ void withinGate(u64& VX, u64& VY, const u64* g)
{
    const u64 A = g[0], D = g[5], ND = g[6];
    const u64 Bm = g[7], NBm = g[8], Cm = g[9];
    u64 ox = swap64(VX), oy = swap64(VY);
    u64 nx = pfma(A, VX, pfma(NBm, VY, pfma(Cm, ox, pmul(ND, oy))));
    u64 ny = pfma(A, VY, pfma(Bm,  VX, pfma(Cm, oy, pmul(D,  ox))));
    VX = nx; VY = ny;
}

// outMode: 0 = real-part only (128,1024) f32; 1 = planar re-block then im-block
__global__ __launch_bounds__(THREADS)
void UnitaryR3Ansatz_kernel(const float* __restrict__ inp,
                            const float* __restrict__ params,
                            float* __restrict__ outF,
                            int outMode)
{
    const int b    = blockIdx.x;    // row 0..127
    const int copy = b >> 2;        // jnp.repeat(M, 4)
    const int t    = threadIdx.x;   // 0..511
    const int l    = t & 31;
    const int w    = t >> 5;        // 0..15

    __shared__ __align__(16) u64 cf[LAYERS][NQ][CFS];
    __shared__ float X0[PLANE], Y0[PLANE];   // A->B buffer
    __shared__ float X1[PLANE], Y1[PLANE];   // B->A buffer

    // --- build coefficient tables (reference _r3 verbatim + SU(2) reduction) ---
    if (t < LAYERS * NQ) {
        const int layer = t / NQ, q = t - layer * NQ;
        const float* a = params + ((size_t)(copy * LAYERS + layer) * NQ + q) * 3;
        const float omega = a[0], theta = a[1], phi = a[2];
        float s,  c;  sincosf(0.5f * theta,         &s,  &c);
        float sp, cp; sincosf(0.5f * (phi + omega), &sp, &cp);
        float sm, cm; sincosf(0.5f * (phi - omega), &sm, &cm);
        const float m11x =  cp * c, m11y = -sp * c;   // m11 = e^{-i(phi+omega)/2} c
        const float m12x = -cm * s, m12y = -sm * s;   // m12 = -e^{+i(phi-omega)/2} s
        u64* g = cf[layer][q];
        g[0] = dup2(m11x);
        g[1] = dup2(m11y);   g[2] = dup2(-m11y);
        g[3] = dup2(m12x);   g[4] = dup2(-m12x);
        g[5] = dup2(m12y);   g[6] = dup2(-m12y);
        g[7] = pack2(m11y, -m11y);
        g[8] = pack2(-m11y, m11y);
        g[9] = pack2(m12x, -m12x);
    }

    // --- per-thread constants ---
    // layout A: j = [warp(4)=j9:6 | lane(5)=j5:1 | half(1)=j0],  jA = (w<<6)|(l<<1)|r
    // layout B: j = [half(1)=j9 | bits j8:4 = lane | j3:0 = warp], jB = (r<<9)|(l<<4)|w
    u64 S[5];
    #pragma unroll
    for (int k = 0; k < 5; ++k)
        S[k] = ((l >> k) & 1) ? 0x8000000080000000ull : 0ull;

    const int jA0 = (w << 6) | (l << 1);
    const int stA = padi(jA0);                       // u64-aligned (even) smem slot
    const int iB0 = padi((l << 4) | w);
    const int iB1 = padi(((l << 4) | w) + 512);
    const int iE0 = padi(sp10(jA0));
    const int iE1 = padi(sp10(jA0 | 1));             // = iE0 ^ adjacency (pre-pad pair)

    // --- load input (layout A, coalesced float2) ---
    const float2 in2 = *(const float2*)(inp + (size_t)b * DIM + jA0);
    u64 VX = pack2(in2.x, in2.y);
    u64 VY = 0;

    __syncthreads();   // coefficient tables ready

    #pragma unroll 1
    for (int layer = 0; layer < LAYERS; ++layer) {
        const u64 (*G)[CFS] = cf[layer];

        // ===== layout A: qubit 9 within-pack; qubits 8..4 on lane bits 0..4 =====
        withinGate(VX, VY, G[9]);
        laneGate(VX, VY,  1, G[8], S[0]);
        laneGate(VX, VY,  2, G[7], S[1]);
        laneGate(VX, VY,  4, G[6], S[2]);
        laneGate(VX, VY,  8, G[5], S[3]);
        laneGate(VX, VY, 16, G[4], S[4]);

        // ===== remap A -> B =====
        *(u64*)(X0 + stA) = VX;
        *(u64*)(Y0 + stA) = VY;
        __syncthreads();
        VX = pack2(X0[iB0], X0[iB1]);
        VY = pack2(Y0[iB0], Y0[iB1]);

        // ===== layout B: qubit 0 within-pack; qubits 1..3 on lane bits 4..2 =====
        withinGate(VX, VY, G[0]);
        laneGate(VX, VY, 16, G[1], S[4]);
        laneGate(VX, VY,  8, G[2], S[3]);
        laneGate(VX, VY,  4, G[3], S[2]);

        // ===== remap B -> A composed with entangler =====
        {
            float f0, f1;
            unpack2(VX, f0, f1);  X1[iB0] = f0;  X1[iB1] = f1;
            unpack2(VY, f0, f1);  Y1[iB0] = f0;  Y1[iB1] = f1;
        }
        __syncthreads();
        VX = pack2(X1[iE0], X1[iE1]);
        VY = pack2(Y1[iE0], Y1[iE1]);
    }

    // --- output (layout A, coalesced float2 pairs) ---
    float x0, x1;
    unpack2(VX, x0, x1);
    *(float2*)(outF + (size_t)b * DIM + jA0) = make_float2(x0, x1);
    if (outMode != 0) {
        float y0, y1;
        unpack2(VY, y0, y1);
        *(float2*)(outF + (size_t)(128 * DIM) + (size_t)b * DIM + jA0) =
            make_float2(y0, y1);
    }
}

extern "C" void kernel_launch(void* const* d_in, const int* in_sizes, int n_in,
                              void* d_out, int out_size)
{
    const float* inp    = (const float*)d_in[0];
    const float* params = (const float*)d_in[1];
    if (n_in >= 2 && in_sizes[0] < in_sizes[1]) {
        inp    = (const float*)d_in[1];
        params = (const float*)d_in[0];
    }
    const int outMode = (out_size == 128 * DIM) ? 0 : 1;

    UnitaryR3Ansatz_kernel<<<128, THREADS>>>(inp, params, (float*)d_out, outMode);
}

// round 12
// speedup vs baseline: 1.1003x; 1.1003x over previous
#include <cuda_runtime.h>
#include <cuda_bf16.h>

#define NQ      10
#define DIM     1024
#define LAYERS  8
#define THREADS 512
#define PLANE   1088
#define CFS     8     // u64 slots per gate: [A,B,C,D,Bm,Cm,pad,pad] (64B aligned)

typedef unsigned long long u64;
#define SGN 0x8000000080000000ull

__device__ __forceinline__ int sp10(int x) {
    // suffix parity: bit p = XOR of bits p..9  (CNOT-chain permutation)
    x ^= x >> 1; x ^= x >> 2; x ^= x >> 4; x ^= x >> 8;
    return x;
}
__device__ __forceinline__ int padi(int j) { return j + 2 * (j >> 5); }

__device__ __forceinline__ u64 pfma(u64 a, u64 b, u64 c) {
    u64 d; asm("fma.rn.f32x2 %0, %1, %2, %3;" : "=l"(d) : "l"(a), "l"(b), "l"(c));
    return d;
}
__device__ __forceinline__ u64 pmul(u64 a, u64 b) {
    u64 d; asm("mul.rn.f32x2 %0, %1, %2;" : "=l"(d) : "l"(a), "l"(b));
    return d;
}
__device__ __forceinline__ u64 pack2(float lo, float hi) {
    u64 d; asm("mov.b64 %0, {%1, %2};" : "=l"(d) : "f"(lo), "f"(hi));
    return d;
}
__device__ __forceinline__ void unpack2(u64 v, float& lo, float& hi) {
    asm("mov.b64 {%0, %1}, %2;" : "=f"(lo), "=f"(hi) : "l"(v));
}
__device__ __forceinline__ u64 swap64(u64 v) {
    u64 r;
    asm("{ .reg .b32 lo, hi; mov.b64 {lo, hi}, %1; mov.b64 %0, {hi, lo}; }"
        : "=l"(r) : "l"(v));
    return r;
}
__device__ __forceinline__ u64 dup2(float v) { return pack2(v, v); }

// Lane-shuffle gate (validated R11 algebra, coefficient path rebuilt):
//   loads (A,B) and (C,D) as two LDS.128; all sign variants via register XOR.
//   nx = A vx + (B^Sn) vy + (C^S) ox + (D^SGN) oy
//   ny = A vy + (B^S ) vx + (C^S) oy +  D      ox
__device__ __forceinline__ void laneGate(u64& VX, u64& VY,
                                         int mask, const u64* g, u64 S, u64 Sn)
{
    const ulonglong2 ab = *(const ulonglong2*)(g);       // A, B
    const ulonglong2 cd = *(const ulonglong2*)(g + 2);   // C, D
    u64 ox = __shfl_xor_sync(0xffffffffu, VX, mask);
    u64 oy = __shfl_xor_sync(0xffffffffu, VY, mask);
    const u64 A  = ab.x;
    const u64 Bs = ab.y ^ S, NBs = ab.y ^ Sn;
    const u64 Cs = cd.x ^ S;
    const u64 D  = cd.y,     ND  = cd.y ^ SGN;
    u64 nx = pfma(A, VX, pfma(NBs, VY, pfma(Cs, ox, pmul(ND, oy))));
    u64 ny = pfma(A, VY, pfma(Bs,  VX, pfma(Cs, oy, pmul(D,  ox))));
    VX = nx; VY = ny;
}

// Within-pack gate (pack halves are the gate pair, half0 = gate-bit 0):
//   nx = A vx + (Bm^SGN) vy + Cm ox + (D^SGN) oy
//   ny = A vy +  Bm      vx + Cm oy +  D      ox       (Bm,Cm mixed-sign packs)
__device__ __forceinline__ void withinGate(u64& VX, u64& VY, const u64* g)
{
    const ulonglong2 ab = *(const ulonglong2*)(g);       // A, (B unused)
    const ulonglong2 cd = *(const ulonglong2*)(g + 2);   // (C unused), D
    const ulonglong2 ef = *(const ulonglong2*)(g + 4);   // Bm, Cm
    const u64 A = ab.x, D = cd.y, ND = cd.y ^ SGN;
    const u64 Bm = ef.x, NBm = ef.x ^ SGN, Cm = ef.y;
    u64 ox = swap64(VX), oy = swap64(VY);
    u64 nx = pfma(A, VX, pfma(NBm, VY, pfma(Cm, ox, pmul(ND, oy))));
    u64 ny = pfma(A, VY, pfma(Bm,  VX, pfma(Cm, oy, pmul(D,  ox))));
    VX = nx; VY = ny;
}

// outMode: 0 = real-part only (128,1024) f32; 1 = planar re-block then im-block
__global__ __launch_bounds__(THREADS)
void UnitaryR3Ansatz_kernel(const float* __restrict__ inp,
                            const float* __restrict__ params,
                            float* __restrict__ outF,
                            int outMode)
{
    const int b    = blockIdx.x;    // row 0..127
    const int copy = b >> 2;        // jnp.repeat(M, 4)
    const int t    = threadIdx.x;   // 0..511
    const int l    = t & 31;
    const int w    = t >> 5;        // 0..15

    __shared__ __align__(16) u64 cf[LAYERS][NQ][CFS];
    __shared__ float X0[PLANE], Y0[PLANE];   // A->B buffer
    __shared__ float X1[PLANE], Y1[PLANE];   // B->A buffer

    // --- build coefficient tables (reference _r3 verbatim + SU(2) reduction) ---
    if (t < LAYERS * NQ) {
        const int layer = t / NQ, q = t - layer * NQ;
        const float* a = params + ((size_t)(copy * LAYERS + layer) * NQ + q) * 3;
        const float omega = a[0], theta = a[1], phi = a[2];
        float s,  c;  sincosf(0.5f * theta,         &s,  &c);
        float sp, cp; sincosf(0.5f * (phi + omega), &sp, &cp);
        float sm, cm; sincosf(0.5f * (phi - omega), &sm, &cm);
        const float m11x =  cp * c, m11y = -sp * c;   // m11 = e^{-i(phi+omega)/2} c
        const float m12x = -cm * s, m12y = -sm * s;   // m12 = -e^{+i(phi-omega)/2} s
        u64* g = cf[layer][q];
        g[0] = dup2(m11x);              // A
        g[1] = dup2(m11y);              // B
        g[2] = dup2(m12x);              // C
        g[3] = dup2(m12y);              // D
        g[4] = pack2(m11y, -m11y);      // Bm
        g[5] = pack2(m12x, -m12x);      // Cm
    }

    // --- per-thread constants (identical to validated R11) ---
    // layout A: j = [warp(4)=j9:6 | lane(5)=j5:1 | half(1)=j0]
    // layout B: j = [half(1)=j9 | lane(5)=j8:4 | warp(4)=j3:0]
    u64 S[5], Sn[5];
    #pragma unroll
    for (int k = 0; k < 5; ++k) {
        S[k]  = ((l >> k) & 1) ? SGN : 0ull;
        Sn[k] = S[k] ^ SGN;
    }

    const int jA0 = (w << 6) | (l << 1);
    const int stA = padi(jA0);                       // u64-aligned (even) smem slot
    const int iB0 = padi((l << 4) | w);
    const int iB1 = padi(((l << 4) | w) + 512);
    const int iE0 = padi(sp10(jA0));
    const int iE1 = padi(sp10(jA0 | 1));

    // --- load input (layout A, coalesced float2) ---
    const float2 in2 = *(const float2*)(inp + (size_t)b * DIM + jA0);
    u64 VX = pack2(in2.x, in2.y);
    u64 VY = 0;

    __syncthreads();   // coefficient tables ready

    #pragma unroll 1
    for (int layer = 0; layer < LAYERS; ++layer) {
        const u64 (*G)[CFS] = cf[layer];

        // ===== layout A: qubit 9 within-pack; qubits 8..4 on lane bits 0..4 =====
        withinGate(VX, VY, G[9]);
        laneGate(VX, VY,  1, G[8], S[0], Sn[0]);
        laneGate(VX, VY,  2, G[7], S[1], Sn[1]);
        laneGate(VX, VY,  4, G[6], S[2], Sn[2]);
        laneGate(VX, VY,  8, G[5], S[3], Sn[3]);
        laneGate(VX, VY, 16, G[4], S[4], Sn[4]);

        // ===== remap A -> B =====
        *(u64*)(X0 + stA) = VX;
        *(u64*)(Y0 + stA) = VY;
        __syncthreads();
        VX = pack2(X0[iB0], X0[iB1]);
        VY = pack2(Y0[iB0], Y0[iB1]);

        // ===== layout B: qubit 0 within-pack; qubits 1..3 on lane bits 4..2 =====
        withinGate(VX, VY, G[0]);
        laneGate(VX, VY, 16, G[1], S[4], Sn[4]);
        laneGate(VX, VY,  8, G[2], S[3], Sn[3]);
        laneGate(VX, VY,  4, G[3], S[2], Sn[2]);

        // ===== remap B -> A composed with entangler =====
        {
            float f0, f1;
            unpack2(VX, f0, f1);  X1[iB0] = f0;  X1[iB1] = f1;
            unpack2(VY, f0, f1);  Y1[iB0] = f0;  Y1[iB1] = f1;
        }
        __syncthreads();
        VX = pack2(X1[iE0], X1[iE1]);
        VY = pack2(Y1[iE0], Y1[iE1]);
    }

    // --- output (layout A, coalesced float2 pairs) ---
    float x0, x1;
    unpack2(VX, x0, x1);
    *(float2*)(outF + (size_t)b * DIM + jA0) = make_float2(x0, x1);
    if (outMode != 0) {
        float y0, y1;
        unpack2(VY, y0, y1);
        *(float2*)(outF + (size_t)(128 * DIM) + (size_t)b * DIM + jA0) =
            make_float2(y0, y1);
    }
}

extern "C" void kernel_launch(void* const* d_in, const int* in_sizes, int n_in,
                              void* d_out, int out_size)
{
    const float* inp    = (const float*)d_in[0];
    const float* params = (const float*)d_in[1];
    if (n_in >= 2 && in_sizes[0] < in_sizes[1]) {
        inp    = (const float*)d_in[1];
        params = (const float*)d_in[0];
    }
    const int outMode = (out_size == 128 * DIM) ? 0 : 1;

    UnitaryR3Ansatz_kernel<<<128, THREADS>>>(inp, params, (float*)d_out, outMode);
}